// round 9
// baseline (speedup 1.0000x reference)
#include <cuda_runtime.h>

// Problem constants
static constexpr int Bb = 128;   // batch
static constexpr int Tt = 32;    // time steps
static constexpr int Dd = 128;   // input dim
static constexpr int Hh = 256;   // hidden
static constexpr int Oo = 128;   // output tags
static constexpr int Zz = 384;   // D + H

static constexpr int GRID = 256;     // 32 h-groups x 8 b-groups
static constexpr int NT   = 256;     // 8 warps

// Persistent state (allowed: __device__ globals, no allocation)
__device__ unsigned g_count = 0;
__device__ unsigned g_phase = 0;
__device__ float    g_h[2][Bb * Hh];   // double-buffered hidden state

__global__ __launch_bounds__(NT, 2)
void stpn_persistent_kernel(const float* __restrict__ sentence,  // [B,T,D]
                            const float* __restrict__ h0,        // [B,H]
                            const float* __restrict__ F0,        // [B,H,Z]
                            const float* __restrict__ Wm,        // [H,Z]
                            const float* __restrict__ bias,      // [H]
                            const float* __restrict__ lam,       // [H,Z]
                            const float* __restrict__ gam,       // [H,Z]
                            const float* __restrict__ Wout,      // [O,H]
                            const float* __restrict__ bout,      // [O]
                            float* __restrict__ out)
{
    float* out_tag = out;                       // [B,O]
    float* out_h   = out + Bb * Oo;             // [B,H]
    float* Fm      = out + Bb * Oo + Bb * Hh;   // [B,H,Z]  (working state == output)

    const int tid  = threadIdx.x;
    const int warp = tid >> 5;
    const int lane = tid & 31;
    const int hg   = blockIdx.x >> 3;   // 0..31
    const int bg   = blockIdx.x & 7;    // 0..7
    const int h    = hg * 8 + warp;     // this warp's hidden index
    const int b0   = bg * 16;           // first batch index of this CTA

    // z double buffer: [2][16 batches][384]
    __shared__ __align__(16) float zbuf[2][16 * Zz];

    unsigned base_phase = 0;
    if (tid == 0) base_phase = *((volatile unsigned*)&g_phase);

    // Per-warp parameter rows live in registers for the whole kernel.
    float4 lamv[3], gamv[3], Wv[3];
#pragma unroll
    for (int i = 0; i < 3; i++) {
        int z = i * 128 + lane * 4;
        lamv[i] = *(const float4*)(lam + h * Zz + z);
        gamv[i] = *(const float4*)(gam + h * Zz + z);
        Wv[i]   = *(const float4*)(Wm  + h * Zz + z);
    }
    const float bias_h = bias[h];

    int barnum = 0;
    auto gridbar = [&]() {
        __syncthreads();
        barnum++;
        if (tid == 0) {
            __threadfence();
            unsigned old = atomicAdd(&g_count, 1u);
            if (old == (unsigned)(GRID - 1)) {
                atomicExch(&g_count, 0u);
                __threadfence();
                atomicAdd(&g_phase, 1u);
            } else {
                unsigned want = base_phase + (unsigned)barnum;
                while ((int)(*((volatile unsigned*)&g_phase) - want) < 0)
                    __nanosleep(64);
            }
            __threadfence();
        }
        __syncthreads();
    };

    for (int t = 1; t <= Tt; t++) {
        if (t > 1) gridbar();   // ensures h_{t-1} (written previous step) is visible

        // ---- stage z_t = [x_t ; h_{t-1}] for this CTA's 16 batches ----
        float* buf = zbuf[t & 1];
        const float* hsrc = (t == 1) ? h0 : &g_h[(t - 1) & 1][0];
        {
            const float* xrow = sentence + (size_t)(t - 1) * Dd;
#pragma unroll 4
            for (int bb = 0; bb < 16; bb++) {
                int b = b0 + bb;
                float* dst = buf + bb * Zz;
                for (int z = tid; z < Zz; z += NT) {
                    float v;
                    if (z < Dd) v = xrow[(size_t)b * Tt * Dd + z];
                    else        v = hsrc[b * Hh + (z - Dd)];
                    dst[z] = v;
                }
            }
        }
        __syncthreads();

        const float* zpb0 = zbuf[(t & 1) ^ 1];
        const bool first  = (t == 1);
        const bool last   = (t == Tt);
        float* hdst = &g_h[t & 1][0];

        size_t rowoff = ((size_t)b0 * Hh + h) * (size_t)Zz;
        for (int bb = 0; bb < 16; bb++, rowoff += (size_t)Hh * Zz) {
            int b = b0 + bb;
            const float* zt = buf  + bb * Zz;
            const float* zp = zpb0 + bb * Zz;
            // pending rank-1 scalar: h_{t-1}[b,h] is the h-part of z_t
            float hp = zt[Dd + h];
            const float* Fsrc = first ? (F0 + rowoff) : (Fm + rowoff);

            float acc = 0.f;
            float4 fk[3];
#pragma unroll
            for (int i = 0; i < 3; i++) {
                int z = i * 128 + lane * 4;
                float4 Fv = *(const float4*)(Fsrc + z);
                float4 z4 = *(const float4*)(zt + z);
                float4 f;
                if (first) {
                    f = Fv;   // f = F_0 (given input), no pending update
                } else {
                    float4 zp4 = *(const float4*)(zp + z);
                    // f = lam*F_{t-2} + gamma * h_{t-1}[b,h] * z_{t-1}[b,z]  ( = F_{t-1} )
                    f.x = fmaf(lamv[i].x, Fv.x, gamv[i].x * (hp * zp4.x));
                    f.y = fmaf(lamv[i].y, Fv.y, gamv[i].y * (hp * zp4.y));
                    f.z = fmaf(lamv[i].z, Fv.z, gamv[i].z * (hp * zp4.z));
                    f.w = fmaf(lamv[i].w, Fv.w, gamv[i].w * (hp * zp4.w));
                }
                acc = fmaf(Wv[i].x + f.x, z4.x, acc);
                acc = fmaf(Wv[i].y + f.y, z4.y, acc);
                acc = fmaf(Wv[i].z + f.z, z4.z, acc);
                acc = fmaf(Wv[i].w + f.w, z4.w, acc);
                fk[i] = f;
                if (!last) *(float4*)(Fm + rowoff + z) = f;   // memory <- F_{t-1}
            }
#pragma unroll
            for (int off = 16; off > 0; off >>= 1)
                acc += __shfl_xor_sync(0xffffffffu, acc, off);
            float hn = tanhf(acc + bias_h);
            if (lane == 0) {
                hdst[b * Hh + h] = hn;
                if (last) out_h[b * Hh + h] = hn;
            }
            if (last) {
                // F_T = lam*F_{T-1} + gamma * h_T[b,h] * z_T[b,z], F_{T-1} still in regs
#pragma unroll
                for (int i = 0; i < 3; i++) {
                    int z = i * 128 + lane * 4;
                    float4 z4 = *(const float4*)(zt + z);
                    float4 ft;
                    ft.x = fmaf(lamv[i].x, fk[i].x, gamv[i].x * (hn * z4.x));
                    ft.y = fmaf(lamv[i].y, fk[i].y, gamv[i].y * (hn * z4.y));
                    ft.z = fmaf(lamv[i].z, fk[i].z, gamv[i].z * (hn * z4.z));
                    ft.w = fmaf(lamv[i].w, fk[i].w, gamv[i].w * (hn * z4.w));
                    *(float4*)(Fm + rowoff + z) = ft;
                }
            }
        }
    }

    gridbar();   // h_T visible everywhere

    // ---- tag_space = h_T @ Wout^T + bout : 512 warps x 32 outputs ----
    if (blockIdx.x < 64) {
        const float* hT = &g_h[Tt & 1][0];   // Tt even -> buffer 0
        int wglob = blockIdx.x * 8 + warp;   // 0..511
#pragma unroll
        for (int k = 0; k < 32; k++) {
            int oidx = wglob * 32 + k;       // 0..16383
            int b = oidx >> 7;
            int o = oidx & 127;
            float s = 0.f;
#pragma unroll
            for (int j = 0; j < 8; j++) {
                int hh = lane + 32 * j;
                s = fmaf(hT[b * Hh + hh], Wout[o * Hh + hh], s);
            }
#pragma unroll
            for (int off = 16; off > 0; off >>= 1)
                s += __shfl_xor_sync(0xffffffffu, s, off);
            if (lane == 0) out_tag[oidx] = s + bout[o];
        }
    }
}

extern "C" void kernel_launch(void* const* d_in, const int* in_sizes, int n_in,
                              void* d_out, int out_size)
{
    (void)in_sizes; (void)n_in; (void)out_size;
    const float* sentence = (const float*)d_in[0];
    const float* h0       = (const float*)d_in[1];
    const float* F0       = (const float*)d_in[2];
    const float* Wm       = (const float*)d_in[3];
    const float* bias     = (const float*)d_in[4];
    const float* lam      = (const float*)d_in[5];
    const float* gam      = (const float*)d_in[6];
    const float* Wout     = (const float*)d_in[7];
    const float* bout     = (const float*)d_in[8];
    float* out = (float*)d_out;

    stpn_persistent_kernel<<<GRID, NT>>>(sentence, h0, F0, Wm, bias, lam, gam,
                                         Wout, bout, out);
}